// round 13
// baseline (speedup 1.0000x reference)
#include <cuda_runtime.h>
#include <math.h>
#include <stdint.h>

#define BATCH 32
#define NN    512
#define NF    256
#define NH    8
#define ND    64
#define HDIM  512   // NH*ND
#define NO    128
#define ALPHA 0.2f
#define ACVT  0.01f

// ---------------- scratch (static device globals; no allocation) -------------
__device__ float g_h  [BATCH*NH*NN*ND];        // h[b][h][n][d]
__device__ float g_se1[BATCH*NH*NN];
__device__ float g_us [BATCH*NH*NN];
__device__ float g_ups[BATCH*NH*NN];
__device__ int   g_perm[BATCH*NH*NN];
__device__ float g_e2 [BATCH*NH*NN];
__device__ float g_v  [BATCH*NH*NN];
__device__ float g_vp [BATCH*NH*NN];
__device__ float g_A  [BATCH*NH*(NN+1)*ND];
__device__ float g_Bx [BATCH*NH*(NN+1)*ND];
__device__ float g_QA [BATCH*NH*(NN+1)];
__device__ float g_QB [BATCH*NH*(NN+1)];
__device__ float g_x2 [BATCH*NN*HDIM];
__device__ float g_h2 [BATCH*NN*NO];
__device__ float g_f1 [BATCH*NN];
__device__ float g_f2 [BATCH*NN];
__device__ float g_maxf1[BATCH];
__device__ float g_ms [BATCH*NN];
__device__ float g_izv[BATCH*NN];
__device__ float g_w  [BATCH*NN];

// ---------------- bf16 mma helpers (sm_80+ legacy mma.sync) ------------------
#define MMA_BF16(d, a, b) \
    asm volatile("mma.sync.aligned.m16n8k16.row.col.f32.bf16.bf16.f32 " \
        "{%0,%1,%2,%3}, {%4,%5,%6,%7}, {%8,%9}, {%0,%1,%2,%3};" \
        : "+f"((d)[0]), "+f"((d)[1]), "+f"((d)[2]), "+f"((d)[3]) \
        : "r"((a)[0]), "r"((a)[1]), "r"((a)[2]), "r"((a)[3]), \
          "r"((b)[0]), "r"((b)[1]))

__device__ __forceinline__ uint32_t pack_bf16x2(float lo, float hi) {
    uint32_t r;
    asm("cvt.rn.satfinite.bf16x2.f32 %0, %1, %2;" : "=r"(r) : "f"(hi), "f"(lo));
    return r;
}

// ------ bf16-split tensor NT GEMM: C[M,N] = A[M,K] * B[N,K]^T -----------------
// CTA tile 128 x NT, 8 warps 4(m)x2(n), k-chunk 32 (16 bf16x2 pairs).
// R11-verified structure; NT templated so the N=128 gemm can use 64-col tiles
// (grid 2x128 = 256 CTAs, fixing the 128-CTA underfill seen in R7's profile).
template<int MODE, int NT>
__global__ __launch_bounds__(256) void gemm_bf16(const float* __restrict__ A,
                                                 const float* __restrict__ B,
                                                 int M, int N, int K)
{
    __shared__ __align__(16) uint2 As2[128][17];   // [row][kpair 0..15], +1 pad
    __shared__ __align__(16) uint2 Bs2[NT][17];
    const float* Ap = (MODE == 2) ? g_x2 : A;
    const int tid = threadIdx.x;
    const int lid = tid & 31, wid = tid >> 5;
    const int wm  = (wid >> 1) * 32;
    const int wn  = (wid & 1) * (NT / 2);
    const int bm  = blockIdx.y * 128;
    const int bn  = blockIdx.x * NT;
    const int r4  = lid >> 2;          // groupID 0..7
    const int c4  = lid & 3;           // threadID_in_group 0..3
    constexpr int NTT = NT / 16;       // n8 tiles per warp

    float acc[2][NTT][4];
#pragma unroll
    for (int mt = 0; mt < 2; mt++)
#pragma unroll
        for (int nt = 0; nt < NTT; nt++)
#pragma unroll
            for (int q = 0; q < 4; q++) acc[mt][nt][q] = 0.f;

    for (int k0 = 0; k0 < K; k0 += 32) {
        __syncthreads();
        // ---- staging: f32 -> (hi,lo) bf16x2 pairs, once per chunk ----
        // A: 128 rows x 16 kpairs = 2048 entries
#pragma unroll
        for (int it = 0; it < 8; it++) {
            int p  = it * 256 + tid;
            int r  = p >> 4;
            int kp = p & 15;
            float2 v = *(const float2*)(Ap + (size_t)(bm + r) * K + k0 + 2 * kp);
            uint32_t hw = pack_bf16x2(v.x, v.y);
            float h0 = __uint_as_float(hw << 16);
            float h1 = __uint_as_float(hw & 0xFFFF0000u);
            uint32_t lw = pack_bf16x2(v.x - h0, v.y - h1);
            As2[r][kp] = make_uint2(hw, lw);
        }
        // B: NT rows x 16 kpairs
#pragma unroll
        for (int it = 0; it < NT / 16; it++) {
            int p  = it * 256 + tid;
            int r  = p >> 4;
            int kp = p & 15;
            float2 v = *(const float2*)(B + (size_t)(bn + r) * K + k0 + 2 * kp);
            uint32_t hw = pack_bf16x2(v.x, v.y);
            float h0 = __uint_as_float(hw << 16);
            float h1 = __uint_as_float(hw & 0xFFFF0000u);
            uint32_t lw = pack_bf16x2(v.x - h0, v.y - h1);
            Bs2[r][kp] = make_uint2(hw, lw);
        }
        __syncthreads();

#pragma unroll
        for (int ks = 0; ks < 2; ks++) {
            const int kb = ks * 8;     // pair base of this k16 step
            unsigned ah[2][4], al[2][4];
#pragma unroll
            for (int mt = 0; mt < 2; mt++) {
                int r0 = wm + mt * 16 + r4;
                uint2 p0 = As2[r0    ][kb + c4];
                uint2 p1 = As2[r0 + 8][kb + c4];
                uint2 p2 = As2[r0    ][kb + c4 + 4];
                uint2 p3 = As2[r0 + 8][kb + c4 + 4];
                ah[mt][0] = p0.x; ah[mt][1] = p1.x; ah[mt][2] = p2.x; ah[mt][3] = p3.x;
                al[mt][0] = p0.y; al[mt][1] = p1.y; al[mt][2] = p2.y; al[mt][3] = p3.y;
            }
#pragma unroll
            for (int nt = 0; nt < NTT; nt++) {
                int cn = wn + nt * 8 + r4;
                uint2 q0 = Bs2[cn][kb + c4];
                uint2 q1 = Bs2[cn][kb + c4 + 4];
                unsigned bh[2] = {q0.x, q1.x};
                unsigned bl[2] = {q0.y, q1.y};
#pragma unroll
                for (int mt = 0; mt < 2; mt++) {
                    MMA_BF16(acc[mt][nt], ah[mt], bh);
                    MMA_BF16(acc[mt][nt], al[mt], bh);
                    MMA_BF16(acc[mt][nt], ah[mt], bl);
                }
            }
        }
    }

    // ---- epilogue: c0:(r,c) c1:(r,c+1) c2:(r+8,c) c3:(r+8,c+1) ----
#pragma unroll
    for (int mt = 0; mt < 2; mt++) {
#pragma unroll
        for (int nt = 0; nt < NTT; nt++) {
            int row0 = bm + wm + mt * 16 + r4;
            int col0 = bn + wn + nt * 8 + 2 * c4;
#pragma unroll
            for (int half = 0; half < 2; half++) {
                int row = row0 + half * 8;
                float cv0 = acc[mt][nt][half * 2 + 0];
                float cv1 = acc[mt][nt][half * 2 + 1];
                if (MODE == 0) {
                    int b = row >> 9, n = row & 511;
                    int hh = col0 >> 6, d = col0 & 63;   // col0,col0+1 same head
                    size_t base = (((size_t)(b * NH + hh)) * NN + n) * ND + d;
                    g_h[base]     = cv0;
                    g_h[base + 1] = cv1;
                } else {
                    g_h2[(size_t)row * N + col0]     = cv0;
                    g_h2[(size_t)row * N + col0 + 1] = cv1;
                }
            }
        }
    }
}

// -------- K2: e1,e2 per (b,h); max; bitonic sort of e1; exp factor tables ----
__global__ __launch_bounds__(256) void k2_attn_prep(const float* __restrict__ a1,
                                                    const float* __restrict__ a2)
{
    int bh  = blockIdx.x;
    int h   = bh & 7;
    int tid = threadIdx.x;
    __shared__ float a1s[ND], a2s[ND];
    __shared__ float e2s[NN];
    __shared__ float skey[NN];
    __shared__ int   sidx[NN];
    __shared__ float red[256];

    if (tid < ND) { a1s[tid] = a1[h * ND + tid]; a2s[tid] = a2[h * ND + tid]; }
    __syncthreads();

    const float* hb = g_h + (size_t)bh * NN * ND;
#pragma unroll
    for (int q = 0; q < 2; q++) {
        int n = tid + q * 256;
        const float4* hr = (const float4*)(hb + (size_t)n * ND);
        float s1 = 0.f, s2 = 0.f;
#pragma unroll
        for (int i = 0; i < 16; i++) {
            float4 v = hr[i];
            s1 += v.x*a1s[4*i] + v.y*a1s[4*i+1] + v.z*a1s[4*i+2] + v.w*a1s[4*i+3];
            s2 += v.x*a2s[4*i] + v.y*a2s[4*i+1] + v.z*a2s[4*i+2] + v.w*a2s[4*i+3];
        }
        skey[n] = s1; sidx[n] = n; e2s[n] = s2;
    }
    __syncthreads();

    red[tid] = fmaxf(e2s[tid], e2s[tid + 256]);
    __syncthreads();
    for (int s = 128; s > 0; s >>= 1) {
        if (tid < s) red[tid] = fmaxf(red[tid], red[tid + s]);
        __syncthreads();
    }
    float m2 = red[0];

    for (int ksz = 2; ksz <= NN; ksz <<= 1) {
        for (int j = ksz >> 1; j > 0; j >>= 1) {
            __syncthreads();
#pragma unroll
            for (int q = 0; q < 2; q++) {
                int i   = tid + q * 256;
                int ixj = i ^ j;
                if (ixj > i) {
                    bool up = ((i & ksz) == 0);
                    float ki = skey[i], kj = skey[ixj];
                    if ((ki > kj) == up) {
                        skey[i] = kj; skey[ixj] = ki;
                        int t = sidx[i]; sidx[i] = sidx[ixj]; sidx[ixj] = t;
                    }
                }
            }
        }
    }
    __syncthreads();

    float m1 = skey[NN - 1];
    size_t o = (size_t)bh * NN;
#pragma unroll
    for (int q = 0; q < 2; q++) {
        int t = tid + q * 256;
        float k = skey[t];
        g_se1[o + t]  = k;
        g_us [o + t]  = __expf(k - m1);
        g_ups[o + t]  = __expf(ALPHA * k - m1);
        g_perm[o + t] = sidx[t];
        float e2 = e2s[t];
        g_e2[o + t] = e2;
        g_v [o + t] = __expf(e2 - m2);
        g_vp[o + t] = __expf(ALPHA * e2 - m2);
    }
}

// -------- K3b: segmented-parallel prefix (u'*h) / suffix (u*h) sums ----------
__global__ __launch_bounds__(512) void k3b_prefix()
{
    int bh  = blockIdx.x;
    int tid = threadIdx.x;
    int d   = tid & 63;
    int s   = tid >> 6;
    size_t o  = (size_t)bh * NN;
    size_t oa = (size_t)bh * (NN + 1) * ND;
    size_t oq = (size_t)bh * (NN + 1);
    const float* hb = g_h + (size_t)bh * NN * ND;

    __shared__ float sups[NN], sus[NN];
    __shared__ int   sperm[NN];
    __shared__ float segA[8][64], segB[8][64];
    __shared__ float segQA[8], segQB[8];

    sups[tid]  = g_ups[o + tid];
    sus[tid]   = g_us [o + tid];
    sperm[tid] = g_perm[o + tid];
    __syncthreads();

    const int t0 = s * 64;

    float fa = 0.f, fb = 0.f, qa = 0.f, qb = 0.f;
#pragma unroll 8
    for (int i = 0; i < 64; i++) {
        int t = t0 + i;
        float hv = hb[(size_t)sperm[t] * ND + d];
        fa = fmaf(sups[t], hv, fa);
        fb = fmaf(sus[t],  hv, fb);
        qa += sups[t];
        qb += sus[t];
    }
    segA[s][d] = fa; segB[s][d] = fb;
    if (d == 0) { segQA[s] = qa; segQB[s] = qb; }
    __syncthreads();

    float offA = 0.f, offB = 0.f, offQA = 0.f, offQB = 0.f;
#pragma unroll
    for (int s2 = 0; s2 < 8; s2++) {
        if (s2 < s) { offA += segA[s2][d]; offQA += segQA[s2]; }
        if (s2 > s) { offB += segB[s2][d]; offQB += segQB[s2]; }
    }

    {
        float accA = offA, accQA = offQA;
#pragma unroll 8
        for (int i = 0; i < 64; i++) {
            int t = t0 + i;
            g_A[oa + (size_t)t * ND + d] = accA;
            if (d == 0) g_QA[oq + t] = accQA;
            float hv = hb[(size_t)sperm[t] * ND + d];
            accA = fmaf(sups[t], hv, accA);
            accQA += sups[t];
        }
        if (s == 7) {
            g_A[oa + (size_t)NN * ND + d] = accA;
            if (d == 0) g_QA[oq + NN] = accQA;
        }
    }

    {
        float accB = offB, accQB = offQB;
#pragma unroll 8
        for (int i = 63; i >= 0; i--) {
            int t = t0 + i;
            float hv = hb[(size_t)sperm[t] * ND + d];
            accB = fmaf(sus[t], hv, accB);
            accQB += sus[t];
            g_Bx[oa + (size_t)t * ND + d] = accB;
            if (d == 0) g_QB[oq + t] = accQB;
        }
        if (s == 0) {
            g_Bx[oa + (size_t)NN * ND + d] = 0.f;
            if (d == 0) g_QB[oq + NN] = 0.f;
        }
    }
}

// -------- K3c: all binary searches in parallel, then warp-wide emission ------
__global__ __launch_bounds__(512) void k3c_apply()
{
    int bh = blockIdx.x;
    int b = bh >> 3, h = bh & 7;
    int tid  = threadIdx.x;
    int lane = tid & 31, wid = tid >> 5;
    __shared__ float se1[NN];
    __shared__ float qa[NN + 1], qb[NN + 1];
    __shared__ int   tjs[NN];
    __shared__ float vjs[NN], vpjs[NN], izjs[NN];
    size_t o  = (size_t)bh * NN;
    size_t oa = (size_t)bh * (NN + 1) * ND;
    size_t oq = (size_t)bh * (NN + 1);

    se1[tid] = g_se1[o + tid];
    qa[tid]  = g_QA[oq + tid];
    qb[tid]  = g_QB[oq + tid];
    if (tid == 0) { qa[NN] = g_QA[oq + NN]; qb[NN] = g_QB[oq + NN]; }
    __syncthreads();

    {
        int j = tid;
        float e2 = g_e2[o + j];
        float v  = g_v [o + j];
        float vp = g_vp[o + j];
        float target = -e2;
        int lo = 0, hi = NN;
        while (lo < hi) { int mid = (lo + hi) >> 1; if (se1[mid] < target) lo = mid + 1; else hi = mid; }
        tjs[j]  = lo;
        vjs[j]  = v;
        vpjs[j] = vp;
        izjs[j] = 1.f / (vp * qa[lo] + v * qb[lo]);
    }
    __syncthreads();

#pragma unroll 4
    for (int q = 0; q < 32; q++) {
        int j = wid * 32 + q;
        int t = tjs[j];
        float v  = vjs[j];
        float vp = vpjs[j];
        float iz = izjs[j];
        const float* Ar = g_A  + oa + (size_t)t * ND;
        const float* Br = g_Bx + oa + (size_t)t * ND;
        float o0 = fmaf(vp, Ar[lane],      v * Br[lane])      * iz;
        float o1 = fmaf(vp, Ar[lane + 32], v * Br[lane + 32]) * iz;
        o0 = (o0 >= 0.f) ? o0 : ACVT * o0;
        o1 = (o1 >= 0.f) ? o1 : ACVT * o1;
        float* x2r = g_x2 + ((size_t)(b * NN + j) * HDIM) + h * ND;
        x2r[lane]      = o0;
        x2r[lane + 32] = o1;
    }
}

// -------- K5: f1/f2 = h2 @ a1o/a2o, plus max(f1) per object ------------------
__global__ __launch_bounds__(512) void k5_f(const float* __restrict__ a1o,
                                            const float* __restrict__ a2o)
{
    int b = blockIdx.x, k = threadIdx.x;
    __shared__ float s1[NO], s2[NO];
    __shared__ float red[512];
    if (k < NO) { s1[k] = a1o[k]; s2[k] = a2o[k]; }
    __syncthreads();
    const float4* hr = (const float4*)(g_h2 + (size_t)(b * NN + k) * NO);
    float f1 = 0.f, f2 = 0.f;
#pragma unroll
    for (int i = 0; i < NO / 4; i++) {
        float4 v = hr[i];
        f1 += v.x*s1[4*i] + v.y*s1[4*i+1] + v.z*s1[4*i+2] + v.w*s1[4*i+3];
        f2 += v.x*s2[4*i] + v.y*s2[4*i+1] + v.z*s2[4*i+2] + v.w*s2[4*i+3];
    }
    g_f1[b * NN + k] = f1;
    g_f2[b * NN + k] = f2;

    red[k] = f1;
    __syncthreads();
    for (int s = 256; s > 0; s >>= 1) {
        if (k < s) red[k] = fmaxf(red[k], red[k + s]);
        __syncthreads();
    }
    if (k == 0) g_maxf1[b] = red[0];
}

// -------- K6a: per-row max (closed form) + z_j ------------------------------
__global__ __launch_bounds__(512) void k6a_rows()
{
    int b  = blockIdx.x;
    int jc = blockIdx.y;
    int tid = threadIdx.x;
    int jl = tid & 127, c = tid >> 7;
    __shared__ float f1s[NN];
    __shared__ float red[4][128];

    f1s[tid] = g_f1[b * NN + tid];
    __syncthreads();
    float maxf1 = g_maxf1[b];

    int j = jc * 128 + jl;
    float fj = g_f2[b * NN + j];
    float mraw = maxf1 + fj;
    float m = (mraw >= 0.f) ? mraw : ALPHA * mraw;

    float z = 0.f;
#pragma unroll 4
    for (int kk = c * 128; kk < c * 128 + 128; kk++) {
        float s = f1s[kk] + fj;
        s = (s >= 0.f) ? s : ALPHA * s;
        z += __expf(s - m);
    }
    red[c][jl] = z;
    __syncthreads();
    if (c == 0) {
        float zt = red[0][jl] + red[1][jl] + red[2][jl] + red[3][jl];
        g_ms [b * NN + j] = m;
        g_izv[b * NN + j] = 1.f / zt;
    }
}

// -------- K6b: w[k] = (1/N) sum_j att[j,k] -----------------------------------
__global__ __launch_bounds__(512) void k6b_cols()
{
    int b  = blockIdx.x;
    int kc = blockIdx.y;
    int tid = threadIdx.x;
    int kl = tid & 127, c = tid >> 7;
    __shared__ float f2s[NN], mss[NN], izs[NN];
    __shared__ float red[4][128];

    f2s[tid] = g_f2[b * NN + tid];
    mss[tid] = g_ms[b * NN + tid];
    izs[tid] = g_izv[b * NN + tid];
    __syncthreads();

    int k = kc * 128 + kl;
    float fk = g_f1[b * NN + k];
    float w = 0.f;
#pragma unroll 4
    for (int j = c * 128; j < c * 128 + 128; j++) {
        float s = fk + f2s[j];
        s = (s >= 0.f) ? s : ALPHA * s;
        w += __expf(s - mss[j]) * izs[j];
    }
    red[c][kl] = w;
    __syncthreads();
    if (c == 0) {
        float wt = red[0][kl] + red[1][kl] + red[2][kl] + red[3][kl];
        g_w[b * NN + k] = wt * (1.0f / (float)NN);
    }
}

// -------- K6c: weighted mean over rows + Linear + L2 normalize ---------------
__global__ __launch_bounds__(512) void k6c_final(const float* __restrict__ Wlin,
                                                 const float* __restrict__ blin,
                                                 float* __restrict__ out)
{
    int b = blockIdx.x, tid = threadIdx.x;
    int d = tid & 127, c = tid >> 7;
    __shared__ float ws[NN];
    __shared__ float red[4][NO];
    __shared__ float om[NO], ys[NO], nrm[4];

    ws[tid] = g_w[b * NN + tid];
    __syncthreads();

    float s = 0.f;
#pragma unroll 4
    for (int k = c * 128; k < c * 128 + 128; k++)
        s = fmaf(ws[k], g_h2[(size_t)(b * NN + k) * NO + d], s);
    red[c][d] = s;
    __syncthreads();
    if (c == 0) om[d] = red[0][d] + red[1][d] + red[2][d] + red[3][d];
    __syncthreads();

    if (tid < NO) {
        float y = blin[tid];
        const float* wr = Wlin + (size_t)tid * NO;
#pragma unroll 4
        for (int dd = 0; dd < NO; dd++) y = fmaf(om[dd], wr[dd], y);
        ys[tid] = y;
    }
    __syncthreads();

    if (tid < NO) {
        float v = ys[tid] * ys[tid];
#pragma unroll
        for (int st = 16; st > 0; st >>= 1) v += __shfl_down_sync(0xffffffffu, v, st);
        if ((tid & 31) == 0) nrm[tid >> 5] = v;
    }
    __syncthreads();
    if (tid == 0) {
        float t = nrm[0] + nrm[1] + nrm[2] + nrm[3];
        nrm[0] = fmaxf(sqrtf(t), 1e-12f);
    }
    __syncthreads();
    if (tid < NO) out[b * NO + tid] = ys[tid] / nrm[0];
}

// -----------------------------------------------------------------------------
extern "C" void kernel_launch(void* const* d_in, const int* in_sizes, int n_in,
                              void* d_out, int out_size)
{
    (void)in_sizes; (void)n_in; (void)out_size;
    const float* X    = (const float*)d_in[0];
    const float* Wt   = (const float*)d_in[1];
    const float* a1   = (const float*)d_in[2];
    const float* a2   = (const float*)d_in[3];
    const float* Wout = (const float*)d_in[4];
    const float* a1o  = (const float*)d_in[5];
    const float* a2o  = (const float*)d_in[6];
    const float* Wlin = (const float*)d_in[7];
    const float* blin = (const float*)d_in[8];
    float* out = (float*)d_out;

    // K1: h = X @ Wt^T  (M=16384, N=512, K=256) — identical to R11
    gemm_bf16<0, 128><<<dim3(HDIM / 128, (BATCH * NN) / 128), 256>>>(X, Wt, BATCH * NN, HDIM, NF);
    k2_attn_prep<<<BATCH * NH, 256>>>(a1, a2);
    k3b_prefix<<<BATCH * NH, 512>>>();
    k3c_apply<<<BATCH * NH, 512>>>();
    // K4: h2 = x2 @ Wout^T (M=16384, N=128, K=512) — 64-col tiles -> 256 CTAs
    gemm_bf16<2, 64><<<dim3(NO / 64, (BATCH * NN) / 128), 256>>>(nullptr, Wout, BATCH * NN, NO, HDIM);
    k5_f<<<BATCH, 512>>>(a1o, a2o);
    k6a_rows<<<dim3(BATCH, 4), 512>>>();
    k6b_cols<<<dim3(BATCH, 4), 512>>>();
    k6c_final<<<BATCH, 512>>>(Wlin, blin, out);
}

// round 15
// speedup vs baseline: 1.1479x; 1.1479x over previous
#include <cuda_runtime.h>
#include <math.h>
#include <stdint.h>

#define BATCH 32
#define NN    512
#define NF    256
#define NH    8
#define ND    64
#define HDIM  512   // NH*ND
#define NO    128
#define ALPHA 0.2f
#define ACVT  0.01f

// ---------------- scratch (static device globals; no allocation) -------------
__device__ float g_h  [BATCH*NH*NN*ND];        // h[b][h][n][d]
__device__ float g_se1[BATCH*NH*NN];
__device__ float g_us [BATCH*NH*NN];
__device__ float g_ups[BATCH*NH*NN];
__device__ int   g_perm[BATCH*NH*NN];
__device__ float g_e2 [BATCH*NH*NN];
__device__ float g_v  [BATCH*NH*NN];
__device__ float g_vp [BATCH*NH*NN];
__device__ float g_A  [BATCH*NH*(NN+1)*ND];
__device__ float g_Bx [BATCH*NH*(NN+1)*ND];
__device__ float g_QA [BATCH*NH*(NN+1)];
__device__ float g_QB [BATCH*NH*(NN+1)];
__device__ float g_h2 [BATCH*NN*NO];
__device__ float g_f1 [BATCH*NN];
__device__ float g_f2 [BATCH*NN];
__device__ float g_maxf1[BATCH];
__device__ float g_ms [BATCH*NN];
__device__ float g_izv[BATCH*NN];
__device__ float g_w  [BATCH*NN];
// pre-converted (hi,lo) bf16x2 pair arrays — 16B aligned for uint4 access
__device__ __align__(16) uint2 g_Xb   [BATCH*NN*NF/2];   // [16384][128]
__device__ __align__(16) uint2 g_Wtb  [HDIM*NF/2];       // [512][128]
__device__ __align__(16) uint2 g_Woutb[NO*HDIM/2];       // [128][256]
__device__ __align__(16) uint2 g_x2b  [BATCH*NN*HDIM/2]; // [16384][256]

// ---------------- bf16 helpers ------------------------------------------------
#define MMA_BF16(d, a, b) \
    asm volatile("mma.sync.aligned.m16n8k16.row.col.f32.bf16.bf16.f32 " \
        "{%0,%1,%2,%3}, {%4,%5,%6,%7}, {%8,%9}, {%0,%1,%2,%3};" \
        : "+f"((d)[0]), "+f"((d)[1]), "+f"((d)[2]), "+f"((d)[3]) \
        : "r"((a)[0]), "r"((a)[1]), "r"((a)[2]), "r"((a)[3]), \
          "r"((b)[0]), "r"((b)[1]))

__device__ __forceinline__ uint32_t pack_bf16x2(float lo, float hi) {
    uint32_t r;
    asm("cvt.rn.satfinite.bf16x2.f32 %0, %1, %2;" : "=r"(r) : "f"(hi), "f"(lo));
    return r;
}
__device__ __forceinline__ uint2 split_pair(float2 v) {
    uint32_t hw = pack_bf16x2(v.x, v.y);
    float h0 = __uint_as_float(hw << 16);
    float h1 = __uint_as_float(hw & 0xFFFF0000u);
    uint32_t lw = pack_bf16x2(v.x - h0, v.y - h1);
    return make_uint2(hw, lw);
}

// -------- kconv kernels: destination symbol referenced in DEVICE code --------
// (passing __device__ symbols as host-side kernel args gives the host shadow
//  address — the R12/R14 bug. These kernels bind the symbol in device code.)
__global__ __launch_bounds__(256) void kconv_X(const float* __restrict__ src) {
    int i = blockIdx.x * 256 + threadIdx.x;
    if (i < BATCH*NN*NF/2) g_Xb[i] = split_pair(((const float2*)src)[i]);
}
__global__ __launch_bounds__(256) void kconv_Wt(const float* __restrict__ src) {
    int i = blockIdx.x * 256 + threadIdx.x;
    if (i < HDIM*NF/2) g_Wtb[i] = split_pair(((const float2*)src)[i]);
}
__global__ __launch_bounds__(256) void kconv_Wout(const float* __restrict__ src) {
    int i = blockIdx.x * 256 + threadIdx.x;
    if (i < NO*HDIM/2) g_Woutb[i] = split_pair(((const float2*)src)[i]);
}

// ------ bf16-split tensor NT GEMM from pre-converted pair arrays --------------
// CTA tile 128x128, 8 warps 4(m)x2(n), k-chunk 32 floats (16 pairs = 8 uint4).
// Staging is a pure uint4 copy (no CVT). Fragment/MMA math identical to R11.
// MODE 0: A=g_Xb, B=g_Wtb, scatter g_h.  MODE 2: A=g_x2b, B=g_Woutb -> g_h2.
template<int MODE, int KP>   // KP = pairs per row (K/2)
__global__ __launch_bounds__(256) void gemm_bf16(int Nout)
{
    __shared__ __align__(16) uint2 As2[128][18];
    __shared__ __align__(16) uint2 Bs2[128][18];
    const uint4* Asrc4 = (const uint4*)((MODE == 2) ? g_x2b : g_Xb);
    const uint4* Bsrc4 = (const uint4*)((MODE == 2) ? g_Woutb : g_Wtb);
    constexpr int KP4 = KP / 2;
    constexpr int NCH = KP / 16;

    const int tid = threadIdx.x;
    const int lid = tid & 31, wid = tid >> 5;
    const int wm  = (wid >> 1) * 32;
    const int wn  = (wid & 1) * 64;
    const int bm  = blockIdx.y * 128;
    const int bn  = blockIdx.x * 128;
    const int r4  = lid >> 2;
    const int c4  = lid & 3;

    float acc[2][8][4];
#pragma unroll
    for (int mt = 0; mt < 2; mt++)
#pragma unroll
        for (int nt = 0; nt < 8; nt++)
#pragma unroll
            for (int q = 0; q < 4; q++) acc[mt][nt][q] = 0.f;

    for (int ch = 0; ch < NCH; ch++) {
        const int k40 = ch * 8;
        __syncthreads();
#pragma unroll
        for (int it = 0; it < 4; it++) {
            int e = it * 256 + tid;
            int r = e >> 3, kc4 = e & 7;
            *(uint4*)&As2[r][kc4 * 2] = Asrc4[(size_t)(bm + r) * KP4 + k40 + kc4];
            *(uint4*)&Bs2[r][kc4 * 2] = Bsrc4[(size_t)(bn + r) * KP4 + k40 + kc4];
        }
        __syncthreads();

#pragma unroll
        for (int ks = 0; ks < 2; ks++) {
            const int kb = ks * 8;
            unsigned ah[2][4], al[2][4];
#pragma unroll
            for (int mt = 0; mt < 2; mt++) {
                int r0 = wm + mt * 16 + r4;
                uint2 p0 = As2[r0    ][kb + c4];
                uint2 p1 = As2[r0 + 8][kb + c4];
                uint2 p2 = As2[r0    ][kb + c4 + 4];
                uint2 p3 = As2[r0 + 8][kb + c4 + 4];
                ah[mt][0] = p0.x; ah[mt][1] = p1.x; ah[mt][2] = p2.x; ah[mt][3] = p3.x;
                al[mt][0] = p0.y; al[mt][1] = p1.y; al[mt][2] = p2.y; al[mt][3] = p3.y;
            }
#pragma unroll
            for (int nt = 0; nt < 8; nt++) {
                int cn = wn + nt * 8 + r4;
                uint2 q0 = Bs2[cn][kb + c4];
                uint2 q1 = Bs2[cn][kb + c4 + 4];
                unsigned bh[2] = {q0.x, q1.x};
                unsigned bl[2] = {q0.y, q1.y};
#pragma unroll
                for (int mt = 0; mt < 2; mt++) {
                    MMA_BF16(acc[mt][nt], ah[mt], bh);
                    MMA_BF16(acc[mt][nt], al[mt], bh);
                    MMA_BF16(acc[mt][nt], ah[mt], bl);
                }
            }
        }
    }

    // ---- epilogue: c0:(r,c) c1:(r,c+1) c2:(r+8,c) c3:(r+8,c+1) ----
#pragma unroll
    for (int mt = 0; mt < 2; mt++) {
#pragma unroll
        for (int nt = 0; nt < 8; nt++) {
            int row0 = bm + wm + mt * 16 + r4;
            int col0 = bn + wn + nt * 8 + 2 * c4;
#pragma unroll
            for (int half = 0; half < 2; half++) {
                int row = row0 + half * 8;
                float cv0 = acc[mt][nt][half * 2 + 0];
                float cv1 = acc[mt][nt][half * 2 + 1];
                if (MODE == 0) {
                    int b = row >> 9, n = row & 511;
                    int hh = col0 >> 6, d = col0 & 63;
                    size_t base = (((size_t)(b * NH + hh)) * NN + n) * ND + d;
                    g_h[base]     = cv0;
                    g_h[base + 1] = cv1;
                } else {
                    g_h2[(size_t)row * Nout + col0]     = cv0;
                    g_h2[(size_t)row * Nout + col0 + 1] = cv1;
                }
            }
        }
    }
}

// -------- K2: e1,e2 per (b,h); max; bitonic sort of e1; exp factor tables ----
__global__ __launch_bounds__(256) void k2_attn_prep(const float* __restrict__ a1,
                                                    const float* __restrict__ a2)
{
    int bh  = blockIdx.x;
    int h   = bh & 7;
    int tid = threadIdx.x;
    __shared__ float a1s[ND], a2s[ND];
    __shared__ float e2s[NN];
    __shared__ float skey[NN];
    __shared__ int   sidx[NN];
    __shared__ float red[256];

    if (tid < ND) { a1s[tid] = a1[h * ND + tid]; a2s[tid] = a2[h * ND + tid]; }
    __syncthreads();

    const float* hb = g_h + (size_t)bh * NN * ND;
#pragma unroll
    for (int q = 0; q < 2; q++) {
        int n = tid + q * 256;
        const float4* hr = (const float4*)(hb + (size_t)n * ND);
        float s1 = 0.f, s2 = 0.f;
#pragma unroll
        for (int i = 0; i < 16; i++) {
            float4 v = hr[i];
            s1 += v.x*a1s[4*i] + v.y*a1s[4*i+1] + v.z*a1s[4*i+2] + v.w*a1s[4*i+3];
            s2 += v.x*a2s[4*i] + v.y*a2s[4*i+1] + v.z*a2s[4*i+2] + v.w*a2s[4*i+3];
        }
        skey[n] = s1; sidx[n] = n; e2s[n] = s2;
    }
    __syncthreads();

    red[tid] = fmaxf(e2s[tid], e2s[tid + 256]);
    __syncthreads();
    for (int s = 128; s > 0; s >>= 1) {
        if (tid < s) red[tid] = fmaxf(red[tid], red[tid + s]);
        __syncthreads();
    }
    float m2 = red[0];

    for (int ksz = 2; ksz <= NN; ksz <<= 1) {
        for (int j = ksz >> 1; j > 0; j >>= 1) {
            __syncthreads();
#pragma unroll
            for (int q = 0; q < 2; q++) {
                int i   = tid + q * 256;
                int ixj = i ^ j;
                if (ixj > i) {
                    bool up = ((i & ksz) == 0);
                    float ki = skey[i], kj = skey[ixj];
                    if ((ki > kj) == up) {
                        skey[i] = kj; skey[ixj] = ki;
                        int t = sidx[i]; sidx[i] = sidx[ixj]; sidx[ixj] = t;
                    }
                }
            }
        }
    }
    __syncthreads();

    float m1 = skey[NN - 1];
    size_t o = (size_t)bh * NN;
#pragma unroll
    for (int q = 0; q < 2; q++) {
        int t = tid + q * 256;
        float k = skey[t];
        g_se1[o + t]  = k;
        g_us [o + t]  = __expf(k - m1);
        g_ups[o + t]  = __expf(ALPHA * k - m1);
        g_perm[o + t] = sidx[t];
        float e2 = e2s[t];
        g_e2[o + t] = e2;
        g_v [o + t] = __expf(e2 - m2);
        g_vp[o + t] = __expf(ALPHA * e2 - m2);
    }
}

// -------- K3b: segmented-parallel prefix (u'*h) / suffix (u*h) sums ----------
__global__ __launch_bounds__(512) void k3b_prefix()
{
    int bh  = blockIdx.x;
    int tid = threadIdx.x;
    int d   = tid & 63;
    int s   = tid >> 6;
    size_t o  = (size_t)bh * NN;
    size_t oa = (size_t)bh * (NN + 1) * ND;
    size_t oq = (size_t)bh * (NN + 1);
    const float* hb = g_h + (size_t)bh * NN * ND;

    __shared__ float sups[NN], sus[NN];
    __shared__ int   sperm[NN];
    __shared__ float segA[8][64], segB[8][64];
    __shared__ float segQA[8], segQB[8];

    sups[tid]  = g_ups[o + tid];
    sus[tid]   = g_us [o + tid];
    sperm[tid] = g_perm[o + tid];
    __syncthreads();

    const int t0 = s * 64;

    float fa = 0.f, fb = 0.f, qa = 0.f, qb = 0.f;
#pragma unroll 8
    for (int i = 0; i < 64; i++) {
        int t = t0 + i;
        float hv = hb[(size_t)sperm[t] * ND + d];
        fa = fmaf(sups[t], hv, fa);
        fb = fmaf(sus[t],  hv, fb);
        qa += sups[t];
        qb += sus[t];
    }
    segA[s][d] = fa; segB[s][d] = fb;
    if (d == 0) { segQA[s] = qa; segQB[s] = qb; }
    __syncthreads();

    float offA = 0.f, offB = 0.f, offQA = 0.f, offQB = 0.f;
#pragma unroll
    for (int s2 = 0; s2 < 8; s2++) {
        if (s2 < s) { offA += segA[s2][d]; offQA += segQA[s2]; }
        if (s2 > s) { offB += segB[s2][d]; offQB += segQB[s2]; }
    }

    {
        float accA = offA, accQA = offQA;
#pragma unroll 8
        for (int i = 0; i < 64; i++) {
            int t = t0 + i;
            g_A[oa + (size_t)t * ND + d] = accA;
            if (d == 0) g_QA[oq + t] = accQA;
            float hv = hb[(size_t)sperm[t] * ND + d];
            accA = fmaf(sups[t], hv, accA);
            accQA += sups[t];
        }
        if (s == 7) {
            g_A[oa + (size_t)NN * ND + d] = accA;
            if (d == 0) g_QA[oq + NN] = accQA;
        }
    }

    {
        float accB = offB, accQB = offQB;
#pragma unroll 8
        for (int i = 63; i >= 0; i--) {
            int t = t0 + i;
            float hv = hb[(size_t)sperm[t] * ND + d];
            accB = fmaf(sus[t], hv, accB);
            accQB += sus[t];
            g_Bx[oa + (size_t)t * ND + d] = accB;
            if (d == 0) g_QB[oq + t] = accQB;
        }
        if (s == 0) {
            g_Bx[oa + (size_t)NN * ND + d] = 0.f;
            if (d == 0) g_QB[oq + NN] = 0.f;
        }
    }
}

// -------- K3c: binary searches + emission as bf16 (hi,lo) pairs --------------
__global__ __launch_bounds__(512) void k3c_apply()
{
    int bh = blockIdx.x;
    int b = bh >> 3, h = bh & 7;
    int tid  = threadIdx.x;
    int lane = tid & 31, wid = tid >> 5;
    __shared__ float se1[NN];
    __shared__ float qa[NN + 1], qb[NN + 1];
    __shared__ int   tjs[NN];
    __shared__ float vjs[NN], vpjs[NN];
    size_t o  = (size_t)bh * NN;
    size_t oa = (size_t)bh * (NN + 1) * ND;
    size_t oq = (size_t)bh * (NN + 1);

    se1[tid] = g_se1[o + tid];
    qa[tid]  = g_QA[oq + tid];
    qb[tid]  = g_QB[oq + tid];
    if (tid == 0) { qa[NN] = g_QA[oq + NN]; qb[NN] = g_QB[oq + NN]; }
    __syncthreads();

    __shared__ float izjs[NN];
    {
        int j = tid;
        float e2 = g_e2[o + j];
        float v  = g_v [o + j];
        float vp = g_vp[o + j];
        float target = -e2;
        int lo = 0, hi = NN;
        while (lo < hi) { int mid = (lo + hi) >> 1; if (se1[mid] < target) lo = mid + 1; else hi = mid; }
        tjs[j]  = lo;
        vjs[j]  = v;
        vpjs[j] = vp;
        izjs[j] = 1.f / (vp * qa[lo] + v * qb[lo]);
    }
    __syncthreads();

#pragma unroll 4
    for (int q = 0; q < 32; q++) {
        int j = wid * 32 + q;
        int t = tjs[j];
        float v  = vjs[j];
        float vp = vpjs[j];
        float iz = izjs[j];
        const float2* Ar = (const float2*)(g_A  + oa + (size_t)t * ND);
        const float2* Br = (const float2*)(g_Bx + oa + (size_t)t * ND);
        float2 a  = Ar[lane];      // dims 2*lane, 2*lane+1
        float2 bb = Br[lane];
        float o0 = fmaf(vp, a.x, v * bb.x) * iz;
        float o1 = fmaf(vp, a.y, v * bb.y) * iz;
        o0 = (o0 >= 0.f) ? o0 : ACVT * o0;
        o1 = (o1 >= 0.f) ? o1 : ACVT * o1;
        // pair index h*32+lane covers x2 dims 64h+2lane, 64h+2lane+1
        g_x2b[(size_t)(b * NN + j) * (HDIM / 2) + h * 32 + lane] =
            split_pair(make_float2(o0, o1));
    }
}

// -------- K5: f1/f2 = h2 @ a1o/a2o, plus max(f1) per object ------------------
__global__ __launch_bounds__(512) void k5_f(const float* __restrict__ a1o,
                                            const float* __restrict__ a2o)
{
    int b = blockIdx.x, k = threadIdx.x;
    __shared__ float s1[NO], s2[NO];
    __shared__ float red[512];
    if (k < NO) { s1[k] = a1o[k]; s2[k] = a2o[k]; }
    __syncthreads();
    const float4* hr = (const float4*)(g_h2 + (size_t)(b * NN + k) * NO);
    float f1 = 0.f, f2 = 0.f;
#pragma unroll
    for (int i = 0; i < NO / 4; i++) {
        float4 v = hr[i];
        f1 += v.x*s1[4*i] + v.y*s1[4*i+1] + v.z*s1[4*i+2] + v.w*s1[4*i+3];
        f2 += v.x*s2[4*i] + v.y*s2[4*i+1] + v.z*s2[4*i+2] + v.w*s2[4*i+3];
    }
    g_f1[b * NN + k] = f1;
    g_f2[b * NN + k] = f2;

    red[k] = f1;
    __syncthreads();
    for (int s = 256; s > 0; s >>= 1) {
        if (k < s) red[k] = fmaxf(red[k], red[k + s]);
        __syncthreads();
    }
    if (k == 0) g_maxf1[b] = red[0];
}

// -------- K6a: per-row max (closed form) + z_j ------------------------------
__global__ __launch_bounds__(512) void k6a_rows()
{
    int b  = blockIdx.x;
    int jc = blockIdx.y;
    int tid = threadIdx.x;
    int jl = tid & 127, c = tid >> 7;
    __shared__ float f1s[NN];
    __shared__ float red[4][128];

    f1s[tid] = g_f1[b * NN + tid];
    __syncthreads();
    float maxf1 = g_maxf1[b];

    int j = jc * 128 + jl;
    float fj = g_f2[b * NN + j];
    float mraw = maxf1 + fj;
    float m = (mraw >= 0.f) ? mraw : ALPHA * mraw;

    float z = 0.f;
#pragma unroll 4
    for (int kk = c * 128; kk < c * 128 + 128; kk++) {
        float s = f1s[kk] + fj;
        s = (s >= 0.f) ? s : ALPHA * s;
        z += __expf(s - m);
    }
    red[c][jl] = z;
    __syncthreads();
    if (c == 0) {
        float zt = red[0][jl] + red[1][jl] + red[2][jl] + red[3][jl];
        g_ms [b * NN + j] = m;
        g_izv[b * NN + j] = 1.f / zt;
    }
}

// -------- K6b: w[k] = (1/N) sum_j att[j,k] -----------------------------------
__global__ __launch_bounds__(512) void k6b_cols()
{
    int b  = blockIdx.x;
    int kc = blockIdx.y;
    int tid = threadIdx.x;
    int kl = tid & 127, c = tid >> 7;
    __shared__ float f2s[NN], mss[NN], izs[NN];
    __shared__ float red[4][128];

    f2s[tid] = g_f2[b * NN + tid];
    mss[tid] = g_ms[b * NN + tid];
    izs[tid] = g_izv[b * NN + tid];
    __syncthreads();

    int k = kc * 128 + kl;
    float fk = g_f1[b * NN + k];
    float w = 0.f;
#pragma unroll 4
    for (int j = c * 128; j < c * 128 + 128; j++) {
        float s = fk + f2s[j];
        s = (s >= 0.f) ? s : ALPHA * s;
        w += __expf(s - mss[j]) * izs[j];
    }
    red[c][kl] = w;
    __syncthreads();
    if (c == 0) {
        float wt = red[0][kl] + red[1][kl] + red[2][kl] + red[3][kl];
        g_w[b * NN + k] = wt * (1.0f / (float)NN);
    }
}

// -------- K6c: weighted mean over rows + Linear + L2 normalize ---------------
__global__ __launch_bounds__(512) void k6c_final(const float* __restrict__ Wlin,
                                                 const float* __restrict__ blin,
                                                 float* __restrict__ out)
{
    int b = blockIdx.x, tid = threadIdx.x;
    int d = tid & 127, c = tid >> 7;
    __shared__ float ws[NN];
    __shared__ float red[4][NO];
    __shared__ float om[NO], ys[NO], nrm[4];

    ws[tid] = g_w[b * NN + tid];
    __syncthreads();

    float s = 0.f;
#pragma unroll 4
    for (int k = c * 128; k < c * 128 + 128; k++)
        s = fmaf(ws[k], g_h2[(size_t)(b * NN + k) * NO + d], s);
    red[c][d] = s;
    __syncthreads();
    if (c == 0) om[d] = red[0][d] + red[1][d] + red[2][d] + red[3][d];
    __syncthreads();

    if (tid < NO) {
        float y = blin[tid];
        const float* wr = Wlin + (size_t)tid * NO;
#pragma unroll 4
        for (int dd = 0; dd < NO; dd++) y = fmaf(om[dd], wr[dd], y);
        ys[tid] = y;
    }
    __syncthreads();

    if (tid < NO) {
        float v = ys[tid] * ys[tid];
#pragma unroll
        for (int st = 16; st > 0; st >>= 1) v += __shfl_down_sync(0xffffffffu, v, st);
        if ((tid & 31) == 0) nrm[tid >> 5] = v;
    }
    __syncthreads();
    if (tid == 0) {
        float t = nrm[0] + nrm[1] + nrm[2] + nrm[3];
        nrm[0] = fmaxf(sqrtf(t), 1e-12f);
    }
    __syncthreads();
    if (tid < NO) out[b * NO + tid] = ys[tid] / nrm[0];
}

// -----------------------------------------------------------------------------
extern "C" void kernel_launch(void* const* d_in, const int* in_sizes, int n_in,
                              void* d_out, int out_size)
{
    (void)in_sizes; (void)n_in; (void)out_size;
    const float* X    = (const float*)d_in[0];
    const float* Wt   = (const float*)d_in[1];
    const float* a1   = (const float*)d_in[2];
    const float* a2   = (const float*)d_in[3];
    const float* Wout = (const float*)d_in[4];
    const float* a1o  = (const float*)d_in[5];
    const float* a2o  = (const float*)d_in[6];
    const float* Wlin = (const float*)d_in[7];
    const float* blin = (const float*)d_in[8];
    float* out = (float*)d_out;

    // pre-convert GEMM inputs to (hi,lo) bf16x2 pairs (device-side symbols)
    kconv_X   <<<(BATCH*NN*NF/2 + 255) / 256, 256>>>(X);
    kconv_Wt  <<<(HDIM*NF/2 + 255) / 256, 256>>>(Wt);
    kconv_Wout<<<(NO*HDIM/2 + 255) / 256, 256>>>(Wout);

    // K1: h = X @ Wt^T  (M=16384, N=512, K=256)
    gemm_bf16<0, NF/2><<<dim3(HDIM / 128, (BATCH * NN) / 128), 256>>>(HDIM);
    k2_attn_prep<<<BATCH * NH, 256>>>(a1, a2);
    k3b_prefix<<<BATCH * NH, 512>>>();
    k3c_apply<<<BATCH * NH, 512>>>();
    // K4: h2 = x2 @ Wout^T (M=16384, N=128, K=512)
    gemm_bf16<2, HDIM/2><<<dim3(NO / 128, (BATCH * NN) / 128), 256>>>(NO);
    k5_f<<<BATCH, 512>>>(a1o, a2o);
    k6a_rows<<<dim3(BATCH, 4), 512>>>();
    k6b_cols<<<dim3(BATCH, 4), 512>>>();
    k6c_final<<<BATCH, 512>>>(Wlin, blin, out);
}

// round 16
// speedup vs baseline: 1.1724x; 1.0213x over previous
#include <cuda_runtime.h>
#include <math.h>
#include <stdint.h>

#define BATCH 32
#define NN    512
#define NF    256
#define NH    8
#define ND    64
#define HDIM  512   // NH*ND
#define NO    128
#define ALPHA 0.2f
#define ACVT  0.01f

// ---------------- scratch (static device globals; no allocation) -------------
__device__ float g_h  [BATCH*NH*NN*ND];        // h[b][h][n][d]
__device__ float g_se1[BATCH*NH*NN];
__device__ float g_us [BATCH*NH*NN];
__device__ float g_ups[BATCH*NH*NN];
__device__ int   g_perm[BATCH*NH*NN];
__device__ float g_e2 [BATCH*NH*NN];
__device__ float g_v  [BATCH*NH*NN];
__device__ float g_vp [BATCH*NH*NN];
__device__ float g_A  [BATCH*NH*(NN+1)*ND];
__device__ float g_Bx [BATCH*NH*(NN+1)*ND];
__device__ float g_QA [BATCH*NH*(NN+1)];
__device__ float g_QB [BATCH*NH*(NN+1)];
__device__ float g_h2 [BATCH*NN*NO];
__device__ float g_f1 [BATCH*NN];
__device__ float g_f2 [BATCH*NN];
__device__ float g_maxf1[BATCH];
__device__ float g_ms [BATCH*NN];
__device__ float g_izv[BATCH*NN];
__device__ float g_w  [BATCH*NN];
// pre-converted (hi,lo) bf16x2 pair arrays — 16B aligned for uint4 access
__device__ __align__(16) uint2 g_Xb   [BATCH*NN*NF/2];   // [16384][128]
__device__ __align__(16) uint2 g_Wtb  [HDIM*NF/2];       // [512][128]
__device__ __align__(16) uint2 g_Woutb[NO*HDIM/2];       // [128][256]
__device__ __align__(16) uint2 g_x2b  [BATCH*NN*HDIM/2]; // [16384][256]

// ---------------- bf16 helpers ------------------------------------------------
#define MMA_BF16(d, a, b) \
    asm volatile("mma.sync.aligned.m16n8k16.row.col.f32.bf16.bf16.f32 " \
        "{%0,%1,%2,%3}, {%4,%5,%6,%7}, {%8,%9}, {%0,%1,%2,%3};" \
        : "+f"((d)[0]), "+f"((d)[1]), "+f"((d)[2]), "+f"((d)[3]) \
        : "r"((a)[0]), "r"((a)[1]), "r"((a)[2]), "r"((a)[3]), \
          "r"((b)[0]), "r"((b)[1]))

__device__ __forceinline__ uint32_t pack_bf16x2(float lo, float hi) {
    uint32_t r;
    asm("cvt.rn.satfinite.bf16x2.f32 %0, %1, %2;" : "=r"(r) : "f"(hi), "f"(lo));
    return r;
}
__device__ __forceinline__ uint2 split_pair(float2 v) {
    uint32_t hw = pack_bf16x2(v.x, v.y);
    float h0 = __uint_as_float(hw << 16);
    float h1 = __uint_as_float(hw & 0xFFFF0000u);
    uint32_t lw = pack_bf16x2(v.x - h0, v.y - h1);
    return make_uint2(hw, lw);
}

// XOR swizzle: permutes 16-kpair columns by row (bits 2-3) -> bank-conflict-free
#define SWZ(r, c) ((c) ^ (((r) & 3) << 2))

// -------- kconv kernels: destination symbol referenced in DEVICE code --------
__global__ __launch_bounds__(256) void kconv_X(const float* __restrict__ src) {
    int i = blockIdx.x * 256 + threadIdx.x;
    if (i < BATCH*NN*NF/2) g_Xb[i] = split_pair(((const float2*)src)[i]);
}
__global__ __launch_bounds__(256) void kconv_Wt(const float* __restrict__ src) {
    int i = blockIdx.x * 256 + threadIdx.x;
    if (i < HDIM*NF/2) g_Wtb[i] = split_pair(((const float2*)src)[i]);
}
__global__ __launch_bounds__(256) void kconv_Wout(const float* __restrict__ src) {
    int i = blockIdx.x * 256 + threadIdx.x;
    if (i < NO*HDIM/2) g_Woutb[i] = split_pair(((const float2*)src)[i]);
}

// ------ bf16-split tensor NT GEMM from pre-converted pair arrays --------------
// CTA tile 128x128, 8 warps 4(m)x2(n), k-chunk 32 floats (16 pairs = 8 uint4).
// Smem rows are 128B (no pad) with XOR column swizzle -> conflict-free LDS/STS.
template<int MODE, int KP>   // KP = pairs per row (K/2)
__global__ __launch_bounds__(256) void gemm_bf16(int Nout)
{
    __shared__ __align__(16) uint2 As2[128][16];
    __shared__ __align__(16) uint2 Bs2[128][16];
    const uint4* Asrc4 = (const uint4*)((MODE == 2) ? g_x2b : g_Xb);
    const uint4* Bsrc4 = (const uint4*)((MODE == 2) ? g_Woutb : g_Wtb);
    constexpr int KP4 = KP / 2;
    constexpr int NCH = KP / 16;

    const int tid = threadIdx.x;
    const int lid = tid & 31, wid = tid >> 5;
    const int wm  = (wid >> 1) * 32;
    const int wn  = (wid & 1) * 64;
    const int bm  = blockIdx.y * 128;
    const int bn  = blockIdx.x * 128;
    const int r4  = lid >> 2;
    const int c4  = lid & 3;

    float acc[2][8][4];
#pragma unroll
    for (int mt = 0; mt < 2; mt++)
#pragma unroll
        for (int nt = 0; nt < 8; nt++)
#pragma unroll
            for (int q = 0; q < 4; q++) acc[mt][nt][q] = 0.f;

    for (int ch = 0; ch < NCH; ch++) {
        const int k40 = ch * 8;
        __syncthreads();
        // ---- staging: uint4 copies into swizzled columns ----
#pragma unroll
        for (int it = 0; it < 4; it++) {
            int e = it * 256 + tid;
            int r = e >> 3, kc4 = e & 7;
            int col = SWZ(r, kc4 * 2);
            *(uint4*)&As2[r][col] = Asrc4[(size_t)(bm + r) * KP4 + k40 + kc4];
            *(uint4*)&Bs2[r][col] = Bsrc4[(size_t)(bn + r) * KP4 + k40 + kc4];
        }
        __syncthreads();

#pragma unroll
        for (int ks = 0; ks < 2; ks++) {
            const int kb = ks * 8;
            unsigned ah[2][4], al[2][4];
#pragma unroll
            for (int mt = 0; mt < 2; mt++) {
                int r0 = wm + mt * 16 + r4;
                uint2 p0 = As2[r0    ][SWZ(r0,     kb + c4)];
                uint2 p1 = As2[r0 + 8][SWZ(r0 + 8, kb + c4)];
                uint2 p2 = As2[r0    ][SWZ(r0,     kb + c4 + 4)];
                uint2 p3 = As2[r0 + 8][SWZ(r0 + 8, kb + c4 + 4)];
                ah[mt][0] = p0.x; ah[mt][1] = p1.x; ah[mt][2] = p2.x; ah[mt][3] = p3.x;
                al[mt][0] = p0.y; al[mt][1] = p1.y; al[mt][2] = p2.y; al[mt][3] = p3.y;
            }
#pragma unroll
            for (int nt = 0; nt < 8; nt++) {
                int cn = wn + nt * 8 + r4;
                uint2 q0 = Bs2[cn][SWZ(cn, kb + c4)];
                uint2 q1 = Bs2[cn][SWZ(cn, kb + c4 + 4)];
                unsigned bh[2] = {q0.x, q1.x};
                unsigned bl[2] = {q0.y, q1.y};
#pragma unroll
                for (int mt = 0; mt < 2; mt++) {
                    MMA_BF16(acc[mt][nt], ah[mt], bh);
                    MMA_BF16(acc[mt][nt], al[mt], bh);
                    MMA_BF16(acc[mt][nt], ah[mt], bl);
                }
            }
        }
    }

    // ---- epilogue: c0:(r,c) c1:(r,c+1) c2:(r+8,c) c3:(r+8,c+1) ----
#pragma unroll
    for (int mt = 0; mt < 2; mt++) {
#pragma unroll
        for (int nt = 0; nt < 8; nt++) {
            int row0 = bm + wm + mt * 16 + r4;
            int col0 = bn + wn + nt * 8 + 2 * c4;
#pragma unroll
            for (int half = 0; half < 2; half++) {
                int row = row0 + half * 8;
                float cv0 = acc[mt][nt][half * 2 + 0];
                float cv1 = acc[mt][nt][half * 2 + 1];
                if (MODE == 0) {
                    int b = row >> 9, n = row & 511;
                    int hh = col0 >> 6, d = col0 & 63;
                    size_t base = (((size_t)(b * NH + hh)) * NN + n) * ND + d;
                    g_h[base]     = cv0;
                    g_h[base + 1] = cv1;
                } else {
                    g_h2[(size_t)row * Nout + col0]     = cv0;
                    g_h2[(size_t)row * Nout + col0 + 1] = cv1;
                }
            }
        }
    }
}

// -------- K2: e1,e2 per (b,h); max; bitonic sort of e1; exp factor tables ----
__global__ __launch_bounds__(256) void k2_attn_prep(const float* __restrict__ a1,
                                                    const float* __restrict__ a2)
{
    int bh  = blockIdx.x;
    int h   = bh & 7;
    int tid = threadIdx.x;
    __shared__ float a1s[ND], a2s[ND];
    __shared__ float e2s[NN];
    __shared__ float skey[NN];
    __shared__ int   sidx[NN];
    __shared__ float red[256];

    if (tid < ND) { a1s[tid] = a1[h * ND + tid]; a2s[tid] = a2[h * ND + tid]; }
    __syncthreads();

    const float* hb = g_h + (size_t)bh * NN * ND;
#pragma unroll
    for (int q = 0; q < 2; q++) {
        int n = tid + q * 256;
        const float4* hr = (const float4*)(hb + (size_t)n * ND);
        float s1 = 0.f, s2 = 0.f;
#pragma unroll
        for (int i = 0; i < 16; i++) {
            float4 v = hr[i];
            s1 += v.x*a1s[4*i] + v.y*a1s[4*i+1] + v.z*a1s[4*i+2] + v.w*a1s[4*i+3];
            s2 += v.x*a2s[4*i] + v.y*a2s[4*i+1] + v.z*a2s[4*i+2] + v.w*a2s[4*i+3];
        }
        skey[n] = s1; sidx[n] = n; e2s[n] = s2;
    }
    __syncthreads();

    red[tid] = fmaxf(e2s[tid], e2s[tid + 256]);
    __syncthreads();
    for (int s = 128; s > 0; s >>= 1) {
        if (tid < s) red[tid] = fmaxf(red[tid], red[tid + s]);
        __syncthreads();
    }
    float m2 = red[0];

    for (int ksz = 2; ksz <= NN; ksz <<= 1) {
        for (int j = ksz >> 1; j > 0; j >>= 1) {
            __syncthreads();
#pragma unroll
            for (int q = 0; q < 2; q++) {
                int i   = tid + q * 256;
                int ixj = i ^ j;
                if (ixj > i) {
                    bool up = ((i & ksz) == 0);
                    float ki = skey[i], kj = skey[ixj];
                    if ((ki > kj) == up) {
                        skey[i] = kj; skey[ixj] = ki;
                        int t = sidx[i]; sidx[i] = sidx[ixj]; sidx[ixj] = t;
                    }
                }
            }
        }
    }
    __syncthreads();

    float m1 = skey[NN - 1];
    size_t o = (size_t)bh * NN;
#pragma unroll
    for (int q = 0; q < 2; q++) {
        int t = tid + q * 256;
        float k = skey[t];
        g_se1[o + t]  = k;
        g_us [o + t]  = __expf(k - m1);
        g_ups[o + t]  = __expf(ALPHA * k - m1);
        g_perm[o + t] = sidx[t];
        float e2 = e2s[t];
        g_e2[o + t] = e2;
        g_v [o + t] = __expf(e2 - m2);
        g_vp[o + t] = __expf(ALPHA * e2 - m2);
    }
}

// -------- K3b: segmented-parallel prefix (u'*h) / suffix (u*h) sums ----------
__global__ __launch_bounds__(512) void k3b_prefix()
{
    int bh  = blockIdx.x;
    int tid = threadIdx.x;
    int d   = tid & 63;
    int s   = tid >> 6;
    size_t o  = (size_t)bh * NN;
    size_t oa = (size_t)bh * (NN + 1) * ND;
    size_t oq = (size_t)bh * (NN + 1);
    const float* hb = g_h + (size_t)bh * NN * ND;

    __shared__ float sups[NN], sus[NN];
    __shared__ int   sperm[NN];
    __shared__ float segA[8][64], segB[8][64];
    __shared__ float segQA[8], segQB[8];

    sups[tid]  = g_ups[o + tid];
    sus[tid]   = g_us [o + tid];
    sperm[tid] = g_perm[o + tid];
    __syncthreads();

    const int t0 = s * 64;

    float fa = 0.f, fb = 0.f, qa = 0.f, qb = 0.f;
#pragma unroll 8
    for (int i = 0; i < 64; i++) {
        int t = t0 + i;
        float hv = hb[(size_t)sperm[t] * ND + d];
        fa = fmaf(sups[t], hv, fa);
        fb = fmaf(sus[t],  hv, fb);
        qa += sups[t];
        qb += sus[t];
    }
    segA[s][d] = fa; segB[s][d] = fb;
    if (d == 0) { segQA[s] = qa; segQB[s] = qb; }
    __syncthreads();

    float offA = 0.f, offB = 0.f, offQA = 0.f, offQB = 0.f;
#pragma unroll
    for (int s2 = 0; s2 < 8; s2++) {
        if (s2 < s) { offA += segA[s2][d]; offQA += segQA[s2]; }
        if (s2 > s) { offB += segB[s2][d]; offQB += segQB[s2]; }
    }

    {
        float accA = offA, accQA = offQA;
#pragma unroll 8
        for (int i = 0; i < 64; i++) {
            int t = t0 + i;
            g_A[oa + (size_t)t * ND + d] = accA;
            if (d == 0) g_QA[oq + t] = accQA;
            float hv = hb[(size_t)sperm[t] * ND + d];
            accA = fmaf(sups[t], hv, accA);
            accQA += sups[t];
        }
        if (s == 7) {
            g_A[oa + (size_t)NN * ND + d] = accA;
            if (d == 0) g_QA[oq + NN] = accQA;
        }
    }

    {
        float accB = offB, accQB = offQB;
#pragma unroll 8
        for (int i = 63; i >= 0; i--) {
            int t = t0 + i;
            float hv = hb[(size_t)sperm[t] * ND + d];
            accB = fmaf(sus[t], hv, accB);
            accQB += sus[t];
            g_Bx[oa + (size_t)t * ND + d] = accB;
            if (d == 0) g_QB[oq + t] = accQB;
        }
        if (s == 0) {
            g_Bx[oa + (size_t)NN * ND + d] = 0.f;
            if (d == 0) g_QB[oq + NN] = 0.f;
        }
    }
}

// -------- K3c: binary searches + emission as bf16 (hi,lo) pairs --------------
__global__ __launch_bounds__(512) void k3c_apply()
{
    int bh = blockIdx.x;
    int b = bh >> 3, h = bh & 7;
    int tid  = threadIdx.x;
    int lane = tid & 31, wid = tid >> 5;
    __shared__ float se1[NN];
    __shared__ float qa[NN + 1], qb[NN + 1];
    __shared__ int   tjs[NN];
    __shared__ float vjs[NN], vpjs[NN];
    __shared__ float izjs[NN];
    size_t o  = (size_t)bh * NN;
    size_t oa = (size_t)bh * (NN + 1) * ND;
    size_t oq = (size_t)bh * (NN + 1);

    se1[tid] = g_se1[o + tid];
    qa[tid]  = g_QA[oq + tid];
    qb[tid]  = g_QB[oq + tid];
    if (tid == 0) { qa[NN] = g_QA[oq + NN]; qb[NN] = g_QB[oq + NN]; }
    __syncthreads();

    {
        int j = tid;
        float e2 = g_e2[o + j];
        float v  = g_v [o + j];
        float vp = g_vp[o + j];
        float target = -e2;
        int lo = 0, hi = NN;
        while (lo < hi) { int mid = (lo + hi) >> 1; if (se1[mid] < target) lo = mid + 1; else hi = mid; }
        tjs[j]  = lo;
        vjs[j]  = v;
        vpjs[j] = vp;
        izjs[j] = 1.f / (vp * qa[lo] + v * qb[lo]);
    }
    __syncthreads();

#pragma unroll 4
    for (int q = 0; q < 32; q++) {
        int j = wid * 32 + q;
        int t = tjs[j];
        float v  = vjs[j];
        float vp = vpjs[j];
        float iz = izjs[j];
        const float2* Ar = (const float2*)(g_A  + oa + (size_t)t * ND);
        const float2* Br = (const float2*)(g_Bx + oa + (size_t)t * ND);
        float2 a  = Ar[lane];
        float2 bb = Br[lane];
        float o0 = fmaf(vp, a.x, v * bb.x) * iz;
        float o1 = fmaf(vp, a.y, v * bb.y) * iz;
        o0 = (o0 >= 0.f) ? o0 : ACVT * o0;
        o1 = (o1 >= 0.f) ? o1 : ACVT * o1;
        g_x2b[(size_t)(b * NN + j) * (HDIM / 2) + h * 32 + lane] =
            split_pair(make_float2(o0, o1));
    }
}

// -------- K5: f1/f2 = h2 @ a1o/a2o, plus max(f1) per object ------------------
__global__ __launch_bounds__(512) void k5_f(const float* __restrict__ a1o,
                                            const float* __restrict__ a2o)
{
    int b = blockIdx.x, k = threadIdx.x;
    __shared__ float s1[NO], s2[NO];
    __shared__ float red[512];
    if (k < NO) { s1[k] = a1o[k]; s2[k] = a2o[k]; }
    __syncthreads();
    const float4* hr = (const float4*)(g_h2 + (size_t)(b * NN + k) * NO);
    float f1 = 0.f, f2 = 0.f;
#pragma unroll
    for (int i = 0; i < NO / 4; i++) {
        float4 v = hr[i];
        f1 += v.x*s1[4*i] + v.y*s1[4*i+1] + v.z*s1[4*i+2] + v.w*s1[4*i+3];
        f2 += v.x*s2[4*i] + v.y*s2[4*i+1] + v.z*s2[4*i+2] + v.w*s2[4*i+3];
    }
    g_f1[b * NN + k] = f1;
    g_f2[b * NN + k] = f2;

    red[k] = f1;
    __syncthreads();
    for (int s = 256; s > 0; s >>= 1) {
        if (k < s) red[k] = fmaxf(red[k], red[k + s]);
        __syncthreads();
    }
    if (k == 0) g_maxf1[b] = red[0];
}

// -------- K6a: per-row max (closed form) + z_j ------------------------------
__global__ __launch_bounds__(512) void k6a_rows()
{
    int b  = blockIdx.x;
    int jc = blockIdx.y;
    int tid = threadIdx.x;
    int jl = tid & 127, c = tid >> 7;
    __shared__ float f1s[NN];
    __shared__ float red[4][128];

    f1s[tid] = g_f1[b * NN + tid];
    __syncthreads();
    float maxf1 = g_maxf1[b];

    int j = jc * 128 + jl;
    float fj = g_f2[b * NN + j];
    float mraw = maxf1 + fj;
    float m = (mraw >= 0.f) ? mraw : ALPHA * mraw;

    float z = 0.f;
#pragma unroll 4
    for (int kk = c * 128; kk < c * 128 + 128; kk++) {
        float s = f1s[kk] + fj;
        s = (s >= 0.f) ? s : ALPHA * s;
        z += __expf(s - m);
    }
    red[c][jl] = z;
    __syncthreads();
    if (c == 0) {
        float zt = red[0][jl] + red[1][jl] + red[2][jl] + red[3][jl];
        g_ms [b * NN + j] = m;
        g_izv[b * NN + j] = 1.f / zt;
    }
}

// -------- K6b: w[k] = (1/N) sum_j att[j,k] -----------------------------------
__global__ __launch_bounds__(512) void k6b_cols()
{
    int b  = blockIdx.x;
    int kc = blockIdx.y;
    int tid = threadIdx.x;
    int kl = tid & 127, c = tid >> 7;
    __shared__ float f2s[NN], mss[NN], izs[NN];
    __shared__ float red[4][128];

    f2s[tid] = g_f2[b * NN + tid];
    mss[tid] = g_ms[b * NN + tid];
    izs[tid] = g_izv[b * NN + tid];
    __syncthreads();

    int k = kc * 128 + kl;
    float fk = g_f1[b * NN + k];
    float w = 0.f;
#pragma unroll 4
    for (int j = c * 128; j < c * 128 + 128; j++) {
        float s = fk + f2s[j];
        s = (s >= 0.f) ? s : ALPHA * s;
        w += __expf(s - mss[j]) * izs[j];
    }
    red[c][kl] = w;
    __syncthreads();
    if (c == 0) {
        float wt = red[0][kl] + red[1][kl] + red[2][kl] + red[3][kl];
        g_w[b * NN + k] = wt * (1.0f / (float)NN);
    }
}

// -------- K6c: weighted mean over rows + Linear + L2 normalize ---------------
__global__ __launch_bounds__(512) void k6c_final(const float* __restrict__ Wlin,
                                                 const float* __restrict__ blin,
                                                 float* __restrict__ out)
{
    int b = blockIdx.x, tid = threadIdx.x;
    int d = tid & 127, c = tid >> 7;
    __shared__ float ws[NN];
    __shared__ float red[4][NO];
    __shared__ float om[NO], ys[NO], nrm[4];

    ws[tid] = g_w[b * NN + tid];
    __syncthreads();

    float s = 0.f;
#pragma unroll 4
    for (int k = c * 128; k < c * 128 + 128; k++)
        s = fmaf(ws[k], g_h2[(size_t)(b * NN + k) * NO + d], s);
    red[c][d] = s;
    __syncthreads();
    if (c == 0) om[d] = red[0][d] + red[1][d] + red[2][d] + red[3][d];
    __syncthreads();

    if (tid < NO) {
        float y = blin[tid];
        const float* wr = Wlin + (size_t)tid * NO;
#pragma unroll 4
        for (int dd = 0; dd < NO; dd++) y = fmaf(om[dd], wr[dd], y);
        ys[tid] = y;
    }
    __syncthreads();

    if (tid < NO) {
        float v = ys[tid] * ys[tid];
#pragma unroll
        for (int st = 16; st > 0; st >>= 1) v += __shfl_down_sync(0xffffffffu, v, st);
        if ((tid & 31) == 0) nrm[tid >> 5] = v;
    }
    __syncthreads();
    if (tid == 0) {
        float t = nrm[0] + nrm[1] + nrm[2] + nrm[3];
        nrm[0] = fmaxf(sqrtf(t), 1e-12f);
    }
    __syncthreads();
    if (tid < NO) out[b * NO + tid] = ys[tid] / nrm[0];
}

// -----------------------------------------------------------------------------
extern "C" void kernel_launch(void* const* d_in, const int* in_sizes, int n_in,
                              void* d_out, int out_size)
{
    (void)in_sizes; (void)n_in; (void)out_size;
    const float* X    = (const float*)d_in[0];
    const float* Wt   = (const float*)d_in[1];
    const float* a1   = (const float*)d_in[2];
    const float* a2   = (const float*)d_in[3];
    const float* Wout = (const float*)d_in[4];
    const float* a1o  = (const float*)d_in[5];
    const float* a2o  = (const float*)d_in[6];
    const float* Wlin = (const float*)d_in[7];
    const float* blin = (const float*)d_in[8];
    float* out = (float*)d_out;

    // pre-convert GEMM inputs to (hi,lo) bf16x2 pairs (device-side symbols)
    kconv_X   <<<(BATCH*NN*NF/2 + 255) / 256, 256>>>(X);
    kconv_Wt  <<<(HDIM*NF/2 + 255) / 256, 256>>>(Wt);
    kconv_Wout<<<(NO*HDIM/2 + 255) / 256, 256>>>(Wout);

    // K1: h = X @ Wt^T  (M=16384, N=512, K=256)
    gemm_bf16<0, NF/2><<<dim3(HDIM / 128, (BATCH * NN) / 128), 256>>>(HDIM);
    k2_attn_prep<<<BATCH * NH, 256>>>(a1, a2);
    k3b_prefix<<<BATCH * NH, 512>>>();
    k3c_apply<<<BATCH * NH, 512>>>();
    // K4: h2 = x2 @ Wout^T (M=16384, N=128, K=512)
    gemm_bf16<2, HDIM/2><<<dim3(NO / 128, (BATCH * NN) / 128), 256>>>(NO);
    k5_f<<<BATCH, 512>>>(a1o, a2o);
    k6a_rows<<<dim3(BATCH, 4), 512>>>();
    k6b_cols<<<dim3(BATCH, 4), 512>>>();
    k6c_final<<<BATCH, 512>>>(Wlin, blin, out);
}

// round 17
// speedup vs baseline: 1.2143x; 1.0357x over previous
#include <cuda_runtime.h>
#include <math.h>
#include <stdint.h>

#define BATCH 32
#define NN    512
#define NF    256
#define NH    8
#define ND    64
#define HDIM  512   // NH*ND
#define NO    128
#define ALPHA 0.2f
#define ACVT  0.01f

// ---------------- scratch (static device globals; no allocation) -------------
__device__ float g_h  [BATCH*NH*NN*ND];        // h[b][h][n][d]
__device__ float g_se1[BATCH*NH*NN];
__device__ float g_us [BATCH*NH*NN];
__device__ float g_ups[BATCH*NH*NN];
__device__ int   g_perm[BATCH*NH*NN];
__device__ float g_e2 [BATCH*NH*NN];
__device__ float g_v  [BATCH*NH*NN];
__device__ float g_vp [BATCH*NH*NN];
__device__ float g_A  [BATCH*NH*(NN+1)*ND];
__device__ float g_Bx [BATCH*NH*(NN+1)*ND];
__device__ float g_QA [BATCH*NH*(NN+1)];
__device__ float g_QB [BATCH*NH*(NN+1)];
__device__ float g_h2 [BATCH*NN*NO];
__device__ float g_f1 [BATCH*NN];
__device__ float g_f2 [BATCH*NN];
__device__ float g_maxf1[BATCH];
__device__ float g_ms [BATCH*NN];
__device__ float g_izv[BATCH*NN];
__device__ float g_w  [BATCH*NN];
// pre-converted (hi,lo) bf16x2 pair arrays — 16B aligned for uint4 access
__device__ __align__(16) uint2 g_Xb   [BATCH*NN*NF/2];   // [16384][128]
__device__ __align__(16) uint2 g_Wtb  [HDIM*NF/2];       // [512][128]
__device__ __align__(16) uint2 g_Woutb[NO*HDIM/2];       // [128][256]
__device__ __align__(16) uint2 g_x2b  [BATCH*NN*HDIM/2]; // [16384][256]

// ---------------- bf16 helpers ------------------------------------------------
#define MMA_BF16(d, a, b) \
    asm volatile("mma.sync.aligned.m16n8k16.row.col.f32.bf16.bf16.f32 " \
        "{%0,%1,%2,%3}, {%4,%5,%6,%7}, {%8,%9}, {%0,%1,%2,%3};" \
        : "+f"((d)[0]), "+f"((d)[1]), "+f"((d)[2]), "+f"((d)[3]) \
        : "r"((a)[0]), "r"((a)[1]), "r"((a)[2]), "r"((a)[3]), \
          "r"((b)[0]), "r"((b)[1]))

__device__ __forceinline__ uint32_t pack_bf16x2(float lo, float hi) {
    uint32_t r;
    asm("cvt.rn.satfinite.bf16x2.f32 %0, %1, %2;" : "=r"(r) : "f"(hi), "f"(lo));
    return r;
}
__device__ __forceinline__ uint2 split_pair(float2 v) {
    uint32_t hw = pack_bf16x2(v.x, v.y);
    float h0 = __uint_as_float(hw << 16);
    float h1 = __uint_as_float(hw & 0xFFFF0000u);
    uint32_t lw = pack_bf16x2(v.x - h0, v.y - h1);
    return make_uint2(hw, lw);
}

// XOR swizzle: permutes 16-kpair columns by row (bits 2-3) -> bank-conflict-free
#define SWZ(r, c) ((c) ^ (((r) & 3) << 2))

// -------- kconv kernels: destination symbol referenced in DEVICE code --------
__global__ __launch_bounds__(256) void kconv_X(const float* __restrict__ src) {
    int i = blockIdx.x * 256 + threadIdx.x;
    if (i < BATCH*NN*NF/2) g_Xb[i] = split_pair(((const float2*)src)[i]);
}
__global__ __launch_bounds__(256) void kconv_Wt(const float* __restrict__ src) {
    int i = blockIdx.x * 256 + threadIdx.x;
    if (i < HDIM*NF/2) g_Wtb[i] = split_pair(((const float2*)src)[i]);
}
__global__ __launch_bounds__(256) void kconv_Wout(const float* __restrict__ src) {
    int i = blockIdx.x * 256 + threadIdx.x;
    if (i < NO*HDIM/2) g_Woutb[i] = split_pair(((const float2*)src)[i]);
}

// ------ bf16-split tensor NT GEMM from pre-converted pair arrays --------------
// CTA tile 128 x NT, 8 warps 4(m)x2(n), k-chunk 32 floats (16 pairs = 8 uint4).
// Smem rows are 128B (no pad) with XOR column swizzle -> conflict-free LDS/STS.
template<int MODE, int NT, int KP>   // NT = n tile; KP = pairs per row (K/2)
__global__ __launch_bounds__(256) void gemm_bf16(int Nout)
{
    __shared__ __align__(16) uint2 As2[128][16];
    __shared__ __align__(16) uint2 Bs2[NT][16];
    const uint4* Asrc4 = (const uint4*)((MODE == 2) ? g_x2b : g_Xb);
    const uint4* Bsrc4 = (const uint4*)((MODE == 2) ? g_Woutb : g_Wtb);
    constexpr int KP4 = KP / 2;
    constexpr int NCH = KP / 16;
    constexpr int NTT = NT / 16;       // n8 tiles per warp

    const int tid = threadIdx.x;
    const int lid = tid & 31, wid = tid >> 5;
    const int wm  = (wid >> 1) * 32;
    const int wn  = (wid & 1) * (NT / 2);
    const int bm  = blockIdx.y * 128;
    const int bn  = blockIdx.x * NT;
    const int r4  = lid >> 2;
    const int c4  = lid & 3;

    float acc[2][NTT][4];
#pragma unroll
    for (int mt = 0; mt < 2; mt++)
#pragma unroll
        for (int nt = 0; nt < NTT; nt++)
#pragma unroll
            for (int q = 0; q < 4; q++) acc[mt][nt][q] = 0.f;

    for (int ch = 0; ch < NCH; ch++) {
        const int k40 = ch * 8;
        __syncthreads();
        // ---- staging: uint4 copies into swizzled columns ----
#pragma unroll
        for (int it = 0; it < 4; it++) {          // A: 128 rows x 8 uint4
            int e = it * 256 + tid;
            int r = e >> 3, kc4 = e & 7;
            int col = SWZ(r, kc4 * 2);
            *(uint4*)&As2[r][col] = Asrc4[(size_t)(bm + r) * KP4 + k40 + kc4];
        }
#pragma unroll
        for (int it = 0; it < NT / 32; it++) {    // B: NT rows x 8 uint4
            int e = it * 256 + tid;
            int r = e >> 3, kc4 = e & 7;
            int col = SWZ(r, kc4 * 2);
            *(uint4*)&Bs2[r][col] = Bsrc4[(size_t)(bn + r) * KP4 + k40 + kc4];
        }
        __syncthreads();

#pragma unroll
        for (int ks = 0; ks < 2; ks++) {
            const int kb = ks * 8;
            unsigned ah[2][4], al[2][4];
#pragma unroll
            for (int mt = 0; mt < 2; mt++) {
                int r0 = wm + mt * 16 + r4;
                uint2 p0 = As2[r0    ][SWZ(r0,     kb + c4)];
                uint2 p1 = As2[r0 + 8][SWZ(r0 + 8, kb + c4)];
                uint2 p2 = As2[r0    ][SWZ(r0,     kb + c4 + 4)];
                uint2 p3 = As2[r0 + 8][SWZ(r0 + 8, kb + c4 + 4)];
                ah[mt][0] = p0.x; ah[mt][1] = p1.x; ah[mt][2] = p2.x; ah[mt][3] = p3.x;
                al[mt][0] = p0.y; al[mt][1] = p1.y; al[mt][2] = p2.y; al[mt][3] = p3.y;
            }
#pragma unroll
            for (int nt = 0; nt < NTT; nt++) {
                int cn = wn + nt * 8 + r4;
                uint2 q0 = Bs2[cn][SWZ(cn, kb + c4)];
                uint2 q1 = Bs2[cn][SWZ(cn, kb + c4 + 4)];
                unsigned bh[2] = {q0.x, q1.x};
                unsigned bl[2] = {q0.y, q1.y};
#pragma unroll
                for (int mt = 0; mt < 2; mt++) {
                    MMA_BF16(acc[mt][nt], ah[mt], bh);
                    MMA_BF16(acc[mt][nt], al[mt], bh);
                    MMA_BF16(acc[mt][nt], ah[mt], bl);
                }
            }
        }
    }

    // ---- epilogue: c0:(r,c) c1:(r,c+1) c2:(r+8,c) c3:(r+8,c+1) ----
#pragma unroll
    for (int mt = 0; mt < 2; mt++) {
#pragma unroll
        for (int nt = 0; nt < NTT; nt++) {
            int row0 = bm + wm + mt * 16 + r4;
            int col0 = bn + wn + nt * 8 + 2 * c4;
#pragma unroll
            for (int half = 0; half < 2; half++) {
                int row = row0 + half * 8;
                float cv0 = acc[mt][nt][half * 2 + 0];
                float cv1 = acc[mt][nt][half * 2 + 1];
                if (MODE == 0) {
                    int b = row >> 9, n = row & 511;
                    int hh = col0 >> 6, d = col0 & 63;
                    size_t base = (((size_t)(b * NH + hh)) * NN + n) * ND + d;
                    g_h[base]     = cv0;
                    g_h[base + 1] = cv1;
                } else {
                    g_h2[(size_t)row * Nout + col0]     = cv0;
                    g_h2[(size_t)row * Nout + col0 + 1] = cv1;
                }
            }
        }
    }
}

// -------- K2: e1,e2 per (b,h); max; bitonic sort of e1; exp factor tables ----
__global__ __launch_bounds__(256) void k2_attn_prep(const float* __restrict__ a1,
                                                    const float* __restrict__ a2)
{
    int bh  = blockIdx.x;
    int h   = bh & 7;
    int tid = threadIdx.x;
    __shared__ float a1s[ND], a2s[ND];
    __shared__ float e2s[NN];
    __shared__ float skey[NN];
    __shared__ int   sidx[NN];
    __shared__ float red[256];

    if (tid < ND) { a1s[tid] = a1[h * ND + tid]; a2s[tid] = a2[h * ND + tid]; }
    __syncthreads();

    const float* hb = g_h + (size_t)bh * NN * ND;
#pragma unroll
    for (int q = 0; q < 2; q++) {
        int n = tid + q * 256;
        const float4* hr = (const float4*)(hb + (size_t)n * ND);
        float s1 = 0.f, s2 = 0.f;
#pragma unroll
        for (int i = 0; i < 16; i++) {
            float4 v = hr[i];
            s1 += v.x*a1s[4*i] + v.y*a1s[4*i+1] + v.z*a1s[4*i+2] + v.w*a1s[4*i+3];
            s2 += v.x*a2s[4*i] + v.y*a2s[4*i+1] + v.z*a2s[4*i+2] + v.w*a2s[4*i+3];
        }
        skey[n] = s1; sidx[n] = n; e2s[n] = s2;
    }
    __syncthreads();

    red[tid] = fmaxf(e2s[tid], e2s[tid + 256]);
    __syncthreads();
    for (int s = 128; s > 0; s >>= 1) {
        if (tid < s) red[tid] = fmaxf(red[tid], red[tid + s]);
        __syncthreads();
    }
    float m2 = red[0];

    for (int ksz = 2; ksz <= NN; ksz <<= 1) {
        for (int j = ksz >> 1; j > 0; j >>= 1) {
            __syncthreads();
#pragma unroll
            for (int q = 0; q < 2; q++) {
                int i   = tid + q * 256;
                int ixj = i ^ j;
                if (ixj > i) {
                    bool up = ((i & ksz) == 0);
                    float ki = skey[i], kj = skey[ixj];
                    if ((ki > kj) == up) {
                        skey[i] = kj; skey[ixj] = ki;
                        int t = sidx[i]; sidx[i] = sidx[ixj]; sidx[ixj] = t;
                    }
                }
            }
        }
    }
    __syncthreads();

    float m1 = skey[NN - 1];
    size_t o = (size_t)bh * NN;
#pragma unroll
    for (int q = 0; q < 2; q++) {
        int t = tid + q * 256;
        float k = skey[t];
        g_se1[o + t]  = k;
        g_us [o + t]  = __expf(k - m1);
        g_ups[o + t]  = __expf(ALPHA * k - m1);
        g_perm[o + t] = sidx[t];
        float e2 = e2s[t];
        g_e2[o + t] = e2;
        g_v [o + t] = __expf(e2 - m2);
        g_vp[o + t] = __expf(ALPHA * e2 - m2);
    }
}

// -------- K3b: segmented-parallel prefix (u'*h) / suffix (u*h) sums ----------
__global__ __launch_bounds__(512) void k3b_prefix()
{
    int bh  = blockIdx.x;
    int tid = threadIdx.x;
    int d   = tid & 63;
    int s   = tid >> 6;
    size_t o  = (size_t)bh * NN;
    size_t oa = (size_t)bh * (NN + 1) * ND;
    size_t oq = (size_t)bh * (NN + 1);
    const float* hb = g_h + (size_t)bh * NN * ND;

    __shared__ float sups[NN], sus[NN];
    __shared__ int   sperm[NN];
    __shared__ float segA[8][64], segB[8][64];
    __shared__ float segQA[8], segQB[8];

    sups[tid]  = g_ups[o + tid];
    sus[tid]   = g_us [o + tid];
    sperm[tid] = g_perm[o + tid];
    __syncthreads();

    const int t0 = s * 64;

    float fa = 0.f, fb = 0.f, qa = 0.f, qb = 0.f;
#pragma unroll 8
    for (int i = 0; i < 64; i++) {
        int t = t0 + i;
        float hv = hb[(size_t)sperm[t] * ND + d];
        fa = fmaf(sups[t], hv, fa);
        fb = fmaf(sus[t],  hv, fb);
        qa += sups[t];
        qb += sus[t];
    }
    segA[s][d] = fa; segB[s][d] = fb;
    if (d == 0) { segQA[s] = qa; segQB[s] = qb; }
    __syncthreads();

    float offA = 0.f, offB = 0.f, offQA = 0.f, offQB = 0.f;
#pragma unroll
    for (int s2 = 0; s2 < 8; s2++) {
        if (s2 < s) { offA += segA[s2][d]; offQA += segQA[s2]; }
        if (s2 > s) { offB += segB[s2][d]; offQB += segQB[s2]; }
    }

    {
        float accA = offA, accQA = offQA;
#pragma unroll 8
        for (int i = 0; i < 64; i++) {
            int t = t0 + i;
            g_A[oa + (size_t)t * ND + d] = accA;
            if (d == 0) g_QA[oq + t] = accQA;
            float hv = hb[(size_t)sperm[t] * ND + d];
            accA = fmaf(sups[t], hv, accA);
            accQA += sups[t];
        }
        if (s == 7) {
            g_A[oa + (size_t)NN * ND + d] = accA;
            if (d == 0) g_QA[oq + NN] = accQA;
        }
    }

    {
        float accB = offB, accQB = offQB;
#pragma unroll 8
        for (int i = 63; i >= 0; i--) {
            int t = t0 + i;
            float hv = hb[(size_t)sperm[t] * ND + d];
            accB = fmaf(sus[t], hv, accB);
            accQB += sus[t];
            g_Bx[oa + (size_t)t * ND + d] = accB;
            if (d == 0) g_QB[oq + t] = accQB;
        }
        if (s == 0) {
            g_Bx[oa + (size_t)NN * ND + d] = 0.f;
            if (d == 0) g_QB[oq + NN] = 0.f;
        }
    }
}

// -------- K3c: searches + emission, 2 blocks per (b,h) for chip fill ---------
__global__ __launch_bounds__(512) void k3c_apply()
{
    int bh   = blockIdx.x;
    int half = blockIdx.y;              // 0 or 1: which 256 rows
    int b = bh >> 3, h = bh & 7;
    int tid  = threadIdx.x;
    int lane = tid & 31, wid = tid >> 5;
    __shared__ float se1[NN];
    __shared__ float qa[NN + 1], qb[NN + 1];
    __shared__ int   tjs[256];
    __shared__ float vjs[256], vpjs[256], izjs[256];
    size_t o  = (size_t)bh * NN;
    size_t oa = (size_t)bh * (NN + 1) * ND;
    size_t oq = (size_t)bh * (NN + 1);

    se1[tid] = g_se1[o + tid];
    qa[tid]  = g_QA[oq + tid];
    qb[tid]  = g_QB[oq + tid];
    if (tid == 0) { qa[NN] = g_QA[oq + NN]; qb[NN] = g_QB[oq + NN]; }
    __syncthreads();

    if (tid < 256) {
        int j = half * 256 + tid;
        float e2 = g_e2[o + j];
        float v  = g_v [o + j];
        float vp = g_vp[o + j];
        float target = -e2;
        int lo = 0, hi = NN;
        while (lo < hi) { int mid = (lo + hi) >> 1; if (se1[mid] < target) lo = mid + 1; else hi = mid; }
        tjs[tid]  = lo;
        vjs[tid]  = v;
        vpjs[tid] = vp;
        izjs[tid] = 1.f / (vp * qa[lo] + v * qb[lo]);
    }
    __syncthreads();

#pragma unroll 4
    for (int q = 0; q < 16; q++) {
        int jl = wid * 16 + q;           // 0..255 within this half
        int j  = half * 256 + jl;
        int t  = tjs[jl];
        float v  = vjs[jl];
        float vp = vpjs[jl];
        float iz = izjs[jl];
        const float2* Ar = (const float2*)(g_A  + oa + (size_t)t * ND);
        const float2* Br = (const float2*)(g_Bx + oa + (size_t)t * ND);
        float2 a  = Ar[lane];
        float2 bb = Br[lane];
        float o0 = fmaf(vp, a.x, v * bb.x) * iz;
        float o1 = fmaf(vp, a.y, v * bb.y) * iz;
        o0 = (o0 >= 0.f) ? o0 : ACVT * o0;
        o1 = (o1 >= 0.f) ? o1 : ACVT * o1;
        g_x2b[(size_t)(b * NN + j) * (HDIM / 2) + h * 32 + lane] =
            split_pair(make_float2(o0, o1));
    }
}

// -------- K5: f1/f2 = h2 @ a1o/a2o, plus max(f1) per object ------------------
__global__ __launch_bounds__(512) void k5_f(const float* __restrict__ a1o,
                                            const float* __restrict__ a2o)
{
    int b = blockIdx.x, k = threadIdx.x;
    __shared__ float s1[NO], s2[NO];
    __shared__ float red[512];
    if (k < NO) { s1[k] = a1o[k]; s2[k] = a2o[k]; }
    __syncthreads();
    const float4* hr = (const float4*)(g_h2 + (size_t)(b * NN + k) * NO);
    float f1 = 0.f, f2 = 0.f;
#pragma unroll
    for (int i = 0; i < NO / 4; i++) {
        float4 v = hr[i];
        f1 += v.x*s1[4*i] + v.y*s1[4*i+1] + v.z*s1[4*i+2] + v.w*s1[4*i+3];
        f2 += v.x*s2[4*i] + v.y*s2[4*i+1] + v.z*s2[4*i+2] + v.w*s2[4*i+3];
    }
    g_f1[b * NN + k] = f1;
    g_f2[b * NN + k] = f2;

    red[k] = f1;
    __syncthreads();
    for (int s = 256; s > 0; s >>= 1) {
        if (k < s) red[k] = fmaxf(red[k], red[k + s]);
        __syncthreads();
    }
    if (k == 0) g_maxf1[b] = red[0];
}

// -------- K6a: per-row max (closed form) + z_j ------------------------------
__global__ __launch_bounds__(512) void k6a_rows()
{
    int b  = blockIdx.x;
    int jc = blockIdx.y;
    int tid = threadIdx.x;
    int jl = tid & 127, c = tid >> 7;
    __shared__ float f1s[NN];
    __shared__ float red[4][128];

    f1s[tid] = g_f1[b * NN + tid];
    __syncthreads();
    float maxf1 = g_maxf1[b];

    int j = jc * 128 + jl;
    float fj = g_f2[b * NN + j];
    float mraw = maxf1 + fj;
    float m = (mraw >= 0.f) ? mraw : ALPHA * mraw;

    float z = 0.f;
#pragma unroll 4
    for (int kk = c * 128; kk < c * 128 + 128; kk++) {
        float s = f1s[kk] + fj;
        s = (s >= 0.f) ? s : ALPHA * s;
        z += __expf(s - m);
    }
    red[c][jl] = z;
    __syncthreads();
    if (c == 0) {
        float zt = red[0][jl] + red[1][jl] + red[2][jl] + red[3][jl];
        g_ms [b * NN + j] = m;
        g_izv[b * NN + j] = 1.f / zt;
    }
}

// -------- K6b: w[k] = (1/N) sum_j att[j,k] -----------------------------------
__global__ __launch_bounds__(512) void k6b_cols()
{
    int b  = blockIdx.x;
    int kc = blockIdx.y;
    int tid = threadIdx.x;
    int kl = tid & 127, c = tid >> 7;
    __shared__ float f2s[NN], mss[NN], izs[NN];
    __shared__ float red[4][128];

    f2s[tid] = g_f2[b * NN + tid];
    mss[tid] = g_ms[b * NN + tid];
    izs[tid] = g_izv[b * NN + tid];
    __syncthreads();

    int k = kc * 128 + kl;
    float fk = g_f1[b * NN + k];
    float w = 0.f;
#pragma unroll 4
    for (int j = c * 128; j < c * 128 + 128; j++) {
        float s = fk + f2s[j];
        s = (s >= 0.f) ? s : ALPHA * s;
        w += __expf(s - mss[j]) * izs[j];
    }
    red[c][kl] = w;
    __syncthreads();
    if (c == 0) {
        float wt = red[0][kl] + red[1][kl] + red[2][kl] + red[3][kl];
        g_w[b * NN + k] = wt * (1.0f / (float)NN);
    }
}

// -------- K6c: weighted mean over rows + Linear + L2 normalize ---------------
__global__ __launch_bounds__(512) void k6c_final(const float* __restrict__ Wlin,
                                                 const float* __restrict__ blin,
                                                 float* __restrict__ out)
{
    int b = blockIdx.x, tid = threadIdx.x;
    int d = tid & 127, c = tid >> 7;
    __shared__ float ws[NN];
    __shared__ float red[4][NO];
    __shared__ float om[NO], ys[NO], nrm[4];

    ws[tid] = g_w[b * NN + tid];
    __syncthreads();

    float s = 0.f;
#pragma unroll 4
    for (int k = c * 128; k < c * 128 + 128; k++)
        s = fmaf(ws[k], g_h2[(size_t)(b * NN + k) * NO + d], s);
    red[c][d] = s;
    __syncthreads();
    if (c == 0) om[d] = red[0][d] + red[1][d] + red[2][d] + red[3][d];
    __syncthreads();

    if (tid < NO) {
        float y = blin[tid];
        const float* wr = Wlin + (size_t)tid * NO;
#pragma unroll 4
        for (int dd = 0; dd < NO; dd++) y = fmaf(om[dd], wr[dd], y);
        ys[tid] = y;
    }
    __syncthreads();

    if (tid < NO) {
        float v = ys[tid] * ys[tid];
#pragma unroll
        for (int st = 16; st > 0; st >>= 1) v += __shfl_down_sync(0xffffffffu, v, st);
        if ((tid & 31) == 0) nrm[tid >> 5] = v;
    }
    __syncthreads();
    if (tid == 0) {
        float t = nrm[0] + nrm[1] + nrm[2] + nrm[3];
        nrm[0] = fmaxf(sqrtf(t), 1e-12f);
    }
    __syncthreads();
    if (tid < NO) out[b * NO + tid] = ys[tid] / nrm[0];
}

// -----------------------------------------------------------------------------
extern "C" void kernel_launch(void* const* d_in, const int* in_sizes, int n_in,
                              void* d_out, int out_size)
{
    (void)in_sizes; (void)n_in; (void)out_size;
    const float* X    = (const float*)d_in[0];
    const float* Wt   = (const float*)d_in[1];
    const float* a1   = (const float*)d_in[2];
    const float* a2   = (const float*)d_in[3];
    const float* Wout = (const float*)d_in[4];
    const float* a1o  = (const float*)d_in[5];
    const float* a2o  = (const float*)d_in[6];
    const float* Wlin = (const float*)d_in[7];
    const float* blin = (const float*)d_in[8];
    float* out = (float*)d_out;

    // pre-convert GEMM inputs to (hi,lo) bf16x2 pairs (device-side symbols)
    kconv_X   <<<(BATCH*NN*NF/2 + 255) / 256, 256>>>(X);
    kconv_Wt  <<<(HDIM*NF/2 + 255) / 256, 256>>>(Wt);
    kconv_Wout<<<(NO*HDIM/2 + 255) / 256, 256>>>(Wout);

    // K1: h = X @ Wt^T  (M=16384, N=512, K=256)
    gemm_bf16<0, 128, NF/2><<<dim3(HDIM / 128, (BATCH * NN) / 128), 256>>>(HDIM);
    k2_attn_prep<<<BATCH * NH, 256>>>(a1, a2);
    k3b_prefix<<<BATCH * NH, 512>>>();
    k3c_apply<<<dim3(BATCH * NH, 2), 512>>>();
    // K4: h2 = x2 @ Wout^T (M=16384, N=128, K=512) — 64-col tiles, 256 CTAs
    gemm_bf16<2, 64, HDIM/2><<<dim3(NO / 64, (BATCH * NN) / 128), 256>>>(NO);
    k5_f<<<BATCH, 512>>>(a1o, a2o);
    k6a_rows<<<dim3(BATCH, 4), 512>>>();
    k6b_cols<<<dim3(BATCH, 4), 512>>>();
    k6c_final<<<BATCH, 512>>>(Wlin, blin, out);
}